// round 12
// baseline (speedup 1.0000x reference)
#include <cuda_runtime.h>
#include <cuda_bf16.h>
#include <cstddef>

// hungarian_matcher cost kernel
// out[b, q, j] = 5 * sum_d |pred_boxes[b,q,d] - target_boxes[b*64+j, d]|
//              - softmax(pred_logits[b,q,:])[target_ids[b*64+j]]
//
// R12 = R10 (best dur: block (64,4)=256, QT=20, QPT=5, grid (45,16)=720,
// 12-padded smem tiles, LDS.128 reads) with the main loop software-
// pipelined: ALL 5 pred rows (15 LDS.128) and all 5 negprob scalars are
// loaded into registers first, then pure back-to-back FP, then 5
// independent coalesced STGs. Exposes LDS latency once per thread
// instead of once per iteration.

namespace {

constexpr int BOX  = 11;
constexpr int BOXP = 12;          // padded row, 48B (float4-aligned)
constexpr int NC   = 4;
constexpr int PER  = 64;
constexpr int QT   = 20;          // queries per CTA (900 = 45*20)
constexpr int QPT  = 5;           // queries per thread
constexpr int NT   = PER * 4;     // 256 threads

__global__ __launch_bounds__(NT)
void matcher_kernel(const float* __restrict__ logits,
                    const float* __restrict__ boxes,
                    const float* __restrict__ tboxes,
                    const int*   __restrict__ tids,
                    float* __restrict__ out,
                    int nq)
{
    const int b  = blockIdx.y;
    const int q0 = blockIdx.x * QT;
    const int j  = threadIdx.x;           // target 0..63
    const int qy = threadIdx.y;           // 0..3
    const int t  = qy * PER + j;          // linear tid

    __shared__ float s_tb[PER * BOXP];         // 768 floats, 12-padded rows
    __shared__ float s_pb[QT * BOXP];          // 240 floats, 12-padded rows
    __shared__ float s_negprob[QT * NC];       // 80 floats

    // --- Target boxes: coalesced LDG, padded STS (704 elems, 3 rounds) ---
    for (int i = t; i < PER * BOX; i += NT) {
        const int row = i / BOX, col = i - row * BOX;
        s_tb[row * BOXP + col] = tboxes[(size_t)b * PER * BOX + i];
    }

    // --- Pred boxes for this tile: 220 elems, coalesced LDG, padded STS ---
    if (t < QT * BOX) {
        const int row = t / BOX, col = t - row * BOX;
        s_pb[row * BOXP + col] = boxes[((size_t)b * nq + q0) * BOX + t];
    }

    // --- Softmax rows: thread t < QT handles query q0+t ---
    if (t < QT) {
        const float* lp = logits + ((size_t)b * nq + q0 + t) * NC;
        float l[NC];
        float m = -1e30f;
#pragma unroll
        for (int c = 0; c < NC; c++) { l[c] = lp[c]; m = fmaxf(m, l[c]); }
        float s = 0.0f;
#pragma unroll
        for (int c = 0; c < NC; c++) { l[c] = __expf(l[c] - m); s += l[c]; }
        const float inv = __frcp_rn(s);
#pragma unroll
        for (int c = 0; c < NC; c++) s_negprob[t * NC + c] = -l[c] * inv;
    }

    // Class id (coalesced 4B LDG across j, L1-resident)
    const int cls = tids[b * PER + j];

    __syncthreads();

    // --- Phase 1: ALL shared loads up front ------------------------------
    // Target box: 3 LDS.128, conflict-free (48B thread stride).
    float tb[BOXP];
    {
        const float4* tr = (const float4*)(s_tb + j * BOXP);
#pragma unroll
        for (int v = 0; v < 3; v++) ((float4*)tb)[v] = tr[v];
    }

    // All 5 pred rows (broadcast LDS.128) + 5 negprob scalars.
    float pbf[QPT][BOXP];
    float np[QPT];
#pragma unroll
    for (int k = 0; k < QPT; k++) {
        const int ql = qy * QPT + k;
        const float4* pr = (const float4*)(s_pb + ql * BOXP);
#pragma unroll
        for (int v = 0; v < 3; v++) ((float4*)pbf[k])[v] = pr[v];
        np[k] = s_negprob[ql * NC + cls];
    }

    // --- Phase 2: pure FP, no memory waits -------------------------------
    float r[QPT];
#pragma unroll
    for (int k = 0; k < QPT; k++) {
        float sa = 0.0f, sb = 0.0f;
#pragma unroll
        for (int d = 0; d < BOX; d += 2) {
            sa += fabsf(pbf[k][d] - tb[d]);
            if (d + 1 < BOX) sb += fabsf(pbf[k][d + 1] - tb[d + 1]);
        }
        r[k] = fmaf(5.0f, sa + sb, np[k]);
    }

    // --- Phase 3: 5 independent coalesced stores -------------------------
    float* orow = out + ((size_t)b * nq + q0 + qy * QPT) * PER + j;
#pragma unroll
    for (int k = 0; k < QPT; k++) {
        orow[(size_t)k * PER] = r[k];
    }
}

} // namespace

extern "C" void kernel_launch(void* const* d_in, const int* in_sizes, int n_in,
                              void* d_out, int out_size)
{
    const float* logits = (const float*)d_in[0];
    const float* boxes  = (const float*)d_in[1];
    const float* tboxes = (const float*)d_in[2];
    const int*   tids   = (const int*)d_in[3];
    float* out = (float*)d_out;

    const int n_total = in_sizes[3];                 // 1024
    const int box_dim = in_sizes[2] / n_total;       // 11
    const int bsnq    = in_sizes[1] / box_dim;       // 14400
    const int per     = out_size / bsnq;             // 64
    const int bs      = n_total / per;               // 16
    const int nq      = bsnq / bs;                   // 900

    (void)n_in; (void)box_dim; (void)per;

    dim3 block(PER, 4);
    dim3 grid(nq / QT, bs);                          // (45, 16) = 720
    matcher_kernel<<<grid, block>>>(logits, boxes, tboxes, tids, out, nq);
}

// round 13
// speedup vs baseline: 1.1327x; 1.1327x over previous
#include <cuda_runtime.h>
#include <cuda_bf16.h>
#include <cstddef>

// hungarian_matcher cost kernel
// out[b, q, j] = 5 * sum_d |pred_boxes[b,q,d] - target_boxes[b*64+j, d]|
//              - softmax(pred_logits[b,q,:])[target_ids[b*64+j]]
//
// R13: warp-autonomous layout — NO __syncthreads. Block (32,8)=256,
// grid (45,16)=720 (proven best shape). Warp w = (qy = w>>1, jhalf = w&1)
// owns queries q0+qy*5..+5 and targets jhalf*32..+32. Each warp stages its
// own targets (352 floats) + pred rows (55 floats) into warp-private smem
// and syncs with __syncwarp only. Softmax: lane 4k+c computes
// -softmax(q_k)[c]; lanes fetch their (k, cls) value via __shfl_sync.
// Critical path: LDG -> STS -> WARPSYNC(23cyc) -> compute, with no
// cross-warp barrier skew.

namespace {

constexpr int BOX = 11;
constexpr int NC  = 4;
constexpr int PER = 64;
constexpr int QPT = 5;           // queries per warp
constexpr int QT  = 20;          // queries per CTA (900 = 45*20)
constexpr int NW  = 8;           // warps per CTA
constexpr int NT  = 32 * NW;     // 256 threads

constexpr int TW  = 32 * BOX;    // 352: target floats per warp
constexpr int PW  = QPT * BOX;   // 55: pred floats per warp
constexpr int PWP = 56;          // padded

__global__ __launch_bounds__(NT)
void matcher_kernel(const float* __restrict__ logits,
                    const float* __restrict__ boxes,
                    const float* __restrict__ tboxes,
                    const int*   __restrict__ tids,
                    float* __restrict__ out,
                    int nq)
{
    const int b    = blockIdx.y;
    const int q0   = blockIdx.x * QT;
    const int lane = threadIdx.x;        // 0..31
    const int w    = threadIdx.y;        // 0..7
    const int qy   = w >> 1;             // 0..3
    const int jh   = w & 1;              // 0..1
    const int qw   = q0 + qy * QPT;      // first query of this warp
    const int j    = jh * 32 + lane;     // this lane's target

    __shared__ float s_t[NW][TW];        // warp-private target tiles
    __shared__ float s_p[NW][PWP];       // warp-private pred tiles

    // --- Stage this warp's 32 target rows: 11 coalesced LDG + STS ---
    {
        const float* src = tboxes + ((size_t)b * PER + jh * 32) * BOX;
#pragma unroll
        for (int i = 0; i < BOX; i++) {
            const int s = lane + 32 * i;
            s_t[w][s] = src[s];
        }
    }

    // --- Stage this warp's 5 pred rows: 55 floats, 2 rounds ---
    {
        const float* src = boxes + ((size_t)b * nq + qw) * BOX;
#pragma unroll
        for (int i = 0; i < 2; i++) {
            const int s = lane + 32 * i;
            if (s < PW) s_p[w][s] = src[s];
        }
    }

    // --- Softmax: lane 4k+c (k<5, c<4) computes -softmax(q_k)[c] ---
    float np_lane = 0.0f;
    if (lane < QPT * NC) {
        const int k = lane >> 2, c = lane & 3;
        const float4 lg = *(const float4*)(logits + ((size_t)b * nq + qw + k) * NC);
        const float m = fmaxf(fmaxf(lg.x, lg.y), fmaxf(lg.z, lg.w));
        const float e0 = __expf(lg.x - m), e1 = __expf(lg.y - m);
        const float e2 = __expf(lg.z - m), e3 = __expf(lg.w - m);
        const float inv = __frcp_rn(e0 + e1 + e2 + e3);
        const float ec = (c == 0) ? e0 : (c == 1) ? e1 : (c == 2) ? e2 : e3;
        np_lane = -ec * inv;
    }

    // Class id for this lane's target (coalesced)
    const int cls = tids[b * PER + j];

    __syncwarp();

    // --- Gather the 5 negprob values this lane needs via shuffle ---
    float np[QPT];
#pragma unroll
    for (int k = 0; k < QPT; k++)
        np[k] = __shfl_sync(0xffffffffu, np_lane, (k << 2) | cls);

    // --- Target box -> registers: 11 LDS, stride 11, conflict-free ---
    float tb[BOX];
#pragma unroll
    for (int d = 0; d < BOX; d++) tb[d] = s_t[w][lane * BOX + d];

    // --- 5 query rows; pred LDS are warp-uniform broadcasts ---
    float* orow = out + ((size_t)b * nq + qw) * PER + j;
#pragma unroll
    for (int k = 0; k < QPT; k++) {
        float sa = 0.0f, sb = 0.0f;
#pragma unroll
        for (int d = 0; d < BOX; d += 2) {
            sa += fabsf(s_p[w][k * BOX + d] - tb[d]);
            if (d + 1 < BOX) sb += fabsf(s_p[w][k * BOX + d + 1] - tb[d + 1]);
        }
        orow[(size_t)k * PER] = fmaf(5.0f, sa + sb, np[k]);
    }
}

} // namespace

extern "C" void kernel_launch(void* const* d_in, const int* in_sizes, int n_in,
                              void* d_out, int out_size)
{
    const float* logits = (const float*)d_in[0];
    const float* boxes  = (const float*)d_in[1];
    const float* tboxes = (const float*)d_in[2];
    const int*   tids   = (const int*)d_in[3];
    float* out = (float*)d_out;

    const int n_total = in_sizes[3];                 // 1024
    const int box_dim = in_sizes[2] / n_total;       // 11
    const int bsnq    = in_sizes[1] / box_dim;       // 14400
    const int per     = out_size / bsnq;             // 64
    const int bs      = n_total / per;               // 16
    const int nq      = bsnq / bs;                   // 900

    (void)n_in; (void)box_dim; (void)per;

    dim3 block(32, NW);
    dim3 grid(nq / QT, bs);                          // (45, 16) = 720
    matcher_kernel<<<grid, block>>>(logits, boxes, tboxes, tids, out, nq);
}